// round 12
// baseline (speedup 1.0000x reference)
#include <cuda_runtime.h>
#include <cuda_bf16.h>
#include <math.h>
#include <cstdint>

// ---------------- problem constants ----------------
#define B 2
#define S 4096
#define HID 2048
#define NH 32
#define NKV 8
#define HD 64
#define GROUPS 4
#define BS_ROWS (B * S)     // 8192
#define GK HID              // all GEMMs have K = 2048
#define KITERS (GK / 64)    // 32 k-iterations of 64 bf16 elements

// fat projection output: [8192, 5120] = [q(2048) | k(512) | v(512) | phi(2048)]
#define NCAT 5120
#define QO 0
#define KO 2048
#define VO 2560
#define PO 3072
#define ROPE_END 2560       // cols < ROPE_END get rope+kappa (q and k)

#if defined(__CUDA_ARCH_FEAT_SM103_ALL) || defined(__CUDA_ARCH_FEAT_SM100_ALL)
#define HAS_TCGEN05 1
#else
#define HAS_TCGEN05 0
#endif

// ---------------- generic ptx helpers ----------------
__device__ __forceinline__ uint32_t elect_one_pred() {
    uint32_t pred;
    asm volatile(
        "{\n\t.reg .pred p;\n\t"
        "elect.sync _|p, 0xFFFFFFFF;\n\t"
        "selp.b32 %0, 1, 0, p;\n\t}"
        : "=r"(pred));
    return pred;
}

__device__ __forceinline__ uint32_t smem_u32(const void* p) {
    uint32_t a;
    asm("{ .reg .u64 t; cvta.to.shared.u64 t, %1; cvt.u32.u64 %0, t; }" : "=r"(a) : "l"(p));
    return a;
}

__device__ __forceinline__ uint32_t cluster_rank() {
    uint32_t r;
    asm("mov.u32 %0, %%cluster_ctarank;" : "=r"(r));
    return r;
}

// bf16 2-way split: x = hi + lo, hi = bf16_rn(x)
__device__ __forceinline__ void bf16_split(float x, __nv_bfloat16& h, __nv_bfloat16& l) {
    h = __float2bfloat16(x);
    l = __float2bfloat16(x - __bfloat162float(h));
}

#define MBARRIER_INIT(addr, cnt) \
    asm volatile("mbarrier.init.shared.b64 [%0], %1;" :: "r"((uint32_t)(addr)), "r"((uint32_t)(cnt)) : "memory")
#define MBARRIER_INVAL(addr) \
    asm volatile("mbarrier.inval.shared.b64 [%0];" :: "r"((uint32_t)(addr)) : "memory")

// arrive on rank0's instance of this barrier (release, cluster scope)
#define MBARRIER_ARRIVE_RANK0(local_addr) \
    asm volatile( \
        "{\n\t.reg .b32 remAddr;\n\t" \
        "mapa.shared::cluster.u32 remAddr, %0, 0;\n\t" \
        "mbarrier.arrive.shared::cluster.b64 _, [remAddr];\n\t}" \
        :: "r"((uint32_t)(local_addr)) : "memory")

// BOUNDED wait (~250K polls): broken protocol finishes fast + observable.
__device__ __forceinline__ void mbar_wait_bounded(uint32_t mbar, uint32_t parity) {
    uint32_t done = 0;
    for (int i = 0; i < 250000; ++i) {
        asm volatile(
            "{\n\t.reg .pred p;\n\t"
            "mbarrier.try_wait.parity.acquire.cta.shared::cta.b64 p, [%1], %2;\n\t"
            "selp.b32 %0, 1, 0, p;\n\t}"
            : "=r"(done) : "r"(mbar), "r"(parity) : "memory");
        if (done) break;
    }
}

#define SWZ(o) ((o) ^ (((o) >> 3) & 0x70))

__device__ __forceinline__ void cp_async16(uint32_t dst, const void* src) {
    asm volatile("cp.async.cg.shared.global [%0], [%1], 16;" :: "r"(dst), "l"(src));
}
#define CP_COMMIT() asm volatile("cp.async.commit_group;" ::: "memory")
#define CP_WAIT1()  asm volatile("cp.async.wait_group 1;" ::: "memory")
#define FENCE_PROXY_ASYNC_SHARED_CTA() asm volatile("fence.proxy.async.shared::cta;" ::: "memory")
#define CLUSTER_SYNC() do { \
    asm volatile("barrier.cluster.arrive.aligned;" ::: "memory"); \
    asm volatile("barrier.cluster.wait.aligned;" ::: "memory"); \
} while (0)

// ---------------- tcgen05 helpers (guarded, cta_group::2) ----------------
#if HAS_TCGEN05
#define TCGEN05_ALLOC_CG2(smem_result_addr, nCols) \
    asm volatile("tcgen05.alloc.cta_group::2.sync.aligned.shared::cta.b32 [%0], %1;" \
        :: "r"((uint32_t)(smem_result_addr)), "r"((uint32_t)(nCols)) : "memory")
#define TCGEN05_DEALLOC_CG2(tmem_addr, nCols) \
    asm volatile("tcgen05.dealloc.cta_group::2.sync.aligned.b32 %0, %1;" :: "r"(tmem_addr), "r"((uint32_t)(nCols)))
#define TCGEN05_RELINQUISH_CG2() \
    asm volatile("tcgen05.relinquish_alloc_permit.cta_group::2.sync.aligned;")
#define TCGEN05_COMMIT_MC_CG2(mbar_smem_addr, mask) \
    asm volatile("tcgen05.commit.cta_group::2.mbarrier::arrive::one.shared::cluster.multicast::cluster.b64 [%0], %1;" \
        :: "r"((uint32_t)(mbar_smem_addr)), "h"((uint16_t)(mask)) : "memory")
#define TCGEN05_WAIT_LD()  asm volatile("tcgen05.wait::ld.sync.aligned;" ::: "memory")
#define TCGEN05_FENCE_AFTER()  asm volatile("tcgen05.fence::after_thread_sync;" ::: "memory")
#define TCGEN05_FENCE_BEFORE() asm volatile("tcgen05.fence::before_thread_sync;" ::: "memory")

#define TCGEN05_LD_32X32B_X32(r, tmem_addr) \
    asm volatile( \
        "tcgen05.ld.sync.aligned.32x32b.x32.b32 " \
        "{%0, %1, %2, %3, %4, %5, %6, %7, " \
        " %8, %9, %10, %11, %12, %13, %14, %15, " \
        " %16, %17, %18, %19, %20, %21, %22, %23, " \
        " %24, %25, %26, %27, %28, %29, %30, %31}, [%32];" \
        : "=r"((r)[0]),  "=r"((r)[1]),  "=r"((r)[2]),  "=r"((r)[3]), \
          "=r"((r)[4]),  "=r"((r)[5]),  "=r"((r)[6]),  "=r"((r)[7]), \
          "=r"((r)[8]),  "=r"((r)[9]),  "=r"((r)[10]), "=r"((r)[11]), \
          "=r"((r)[12]), "=r"((r)[13]), "=r"((r)[14]), "=r"((r)[15]), \
          "=r"((r)[16]), "=r"((r)[17]), "=r"((r)[18]), "=r"((r)[19]), \
          "=r"((r)[20]), "=r"((r)[21]), "=r"((r)[22]), "=r"((r)[23]), \
          "=r"((r)[24]), "=r"((r)[25]), "=r"((r)[26]), "=r"((r)[27]), \
          "=r"((r)[28]), "=r"((r)[29]), "=r"((r)[30]), "=r"((r)[31]) \
        : "r"(tmem_addr))

// bf16 cg2 SS MMA (kind::f16) with disable-output-lane vector (8 regs, all 0)
__device__ __forceinline__ void tcgen05_mma_bf16_cg2(uint32_t d, uint64_t ad, uint64_t bd,
                                                     uint32_t idesc, uint32_t en) {
    asm volatile(
        "{\n\t.reg .pred p;\n\t"
        "setp.ne.u32 p, %5, 0;\n\t"
        "tcgen05.mma.cta_group::2.kind::f16 [%0], %1, %2, %3, "
        "{%4, %4, %4, %4, %4, %4, %4, %4}, p;\n\t}"
        :: "r"(d), "l"(ad), "l"(bd), "r"(idesc), "r"(0u), "r"(en) : "memory");
}
#endif // HAS_TCGEN05

static constexpr uint64_t SMEM_DESC_BASE_SW128 =
    (uint64_t(2) << 61) | (uint64_t(1) << 46) | (uint64_t(64) << 32) | (uint64_t(1) << 16);
#define MAKE_SMEM_DESC(base_addr) (SMEM_DESC_BASE_SW128 | ((uint64_t)((base_addr) >> 4) & 0x3FFF))

// ---------------- scratch (static device globals; 256B-aligned) ----------------
__device__ __align__(256) float g_qkvp[(size_t)BS_ROWS * NCAT];   // fat projection output
__device__ __align__(256) float g_ropeC[S * 32];                  // cos table
__device__ __align__(256) float g_ropeS[S * 32];                  // sin table
__device__ __align__(256) float g_Qg [B * NH * HD];
__device__ __align__(256) float g_logits[B * NH * S];
__device__ __align__(256) float g_alpha [B * NH * S];
__device__ __align__(256) float g_M  [B * NH * HD * HD];
// bf16 hi/lo split of the GEMM A operand (hs for projections, then ctx for Wo)
__device__ __align__(256) __nv_bfloat16 g_Ahi[(size_t)BS_ROWS * HID];
__device__ __align__(256) __nv_bfloat16 g_Alo[(size_t)BS_ROWS * HID];
// concatenated transposed weights [5120, 2048] bf16 hi/lo + Wo
__device__ __align__(256) __nv_bfloat16 g_WcatT_hi[(size_t)NCAT * HID];
__device__ __align__(256) __nv_bfloat16 g_WcatT_lo[(size_t)NCAT * HID];
__device__ __align__(256) __nv_bfloat16 g_WoT_hi  [HID * HID];
__device__ __align__(256) __nv_bfloat16 g_WoT_lo  [HID * HID];

// ---------------- cg2 3-term bf16 GEMM -----------------------------------------
#define ROWS_CTA 128
#define PAIR_M 256
#define PAIR_N 256
#define STAGES 3
#define REGION_BYTES (ROWS_CTA * 128)         // 16KB
#define STAGE_BYTES (4 * REGION_BYTES)        // 64KB
#define SM_FULL(s)  (8  + (s) * 8)
#define SM_EMPTY(s) (32 + (s) * 8)
#define SM_DONE 56
#define SM_AHI(s) (1024 + (s) * STAGE_BYTES)
#define SM_ALO(s) (SM_AHI(s) + REGION_BYTES)
#define SM_BHI(s) (SM_AHI(s) + 2 * REGION_BYTES)
#define SM_BLO(s) (SM_AHI(s) + 3 * REGION_BYTES)
#define SMEM_GEMM (1024 + STAGES * STAGE_BYTES)   // 197632 bytes

static constexpr uint32_t IDESC_CG2 =
    (1u << 4)              // dtype F32
  | (1u << 7)              // atype BF16
  | (1u << 10)             // btype BF16
  | ((PAIR_N / 8) << 17)   // N = 256
  | ((PAIR_M / 16) << 24); // M = 256

__device__ __forceinline__ void load_region(uint32_t dst, const __nv_bfloat16* __restrict__ src,
                                            int row0, int k0, int tid) {
    #pragma unroll
    for (int i = 0; i < 4; i++) {
        int chunk = i * 256 + tid;
        int row = chunk >> 3, c = chunk & 7;
        uint32_t off = (uint32_t)(row * 128 + c * 16);
        cp_async16(dst + SWZ(off), src + (size_t)(row0 + row) * GK + k0 + c * 8);
    }
}

__device__ __forceinline__ void load_stage(uint32_t sb, int st,
                                           const __nv_bfloat16* __restrict__ Ahi,
                                           const __nv_bfloat16* __restrict__ Alo,
                                           const __nv_bfloat16* __restrict__ Bhi,
                                           const __nv_bfloat16* __restrict__ Blo,
                                           int aRow0, int bRow0, int k0, int tid) {
    load_region(sb + SM_AHI(st), Ahi, aRow0, k0, tid);
    load_region(sb + SM_ALO(st), Alo, aRow0, k0, tid);
    load_region(sb + SM_BHI(st), Bhi, bRow0, k0, tid);
    load_region(sb + SM_BLO(st), Blo, bRow0, k0, tid);
}

// doRope != 0: columns < ROPE_END of the output get RoPE + kappa in the epilogue.
__global__ __launch_bounds__(256, 1) __cluster_dims__(2, 1, 1)
void tc_gemm(const __nv_bfloat16* __restrict__ Ahi, const __nv_bfloat16* __restrict__ Alo,
             const __nv_bfloat16* __restrict__ Bhi, const __nv_bfloat16* __restrict__ Blo,
             float* __restrict__ C, int N, int doRope) {
    const uint32_t rank = cluster_rank();
    const int m0 = blockIdx.z * PAIR_M;
    const int n0 = blockIdx.y * PAIR_N;
#if HAS_TCGEN05
    extern __shared__ char smem[];
    uint32_t sb = smem_u32(smem);
    const int tid = threadIdx.x;
    const int wid = tid >> 5, lid = tid & 31;
    const int aRow0 = m0 + (int)rank * ROWS_CTA;
    const int bRow0 = n0 + (int)rank * ROWS_CTA;

    if (tid == 0) {
        #pragma unroll
        for (int s = 0; s < STAGES; s++) {
            MBARRIER_INIT(sb + SM_FULL(s), 1);
            MBARRIER_INIT(sb + SM_EMPTY(s), 1);
        }
        MBARRIER_INIT(sb + SM_DONE, 1);
    }
    __syncthreads();
    if (wid == 0) TCGEN05_ALLOC_CG2(sb, 256);
    __syncthreads();
    uint32_t tbase;
    asm volatile("ld.shared.b32 %0, [%1];" : "=r"(tbase) : "r"(sb));

    load_stage(sb, 0, Ahi, Alo, Bhi, Blo, aRow0, bRow0, 0, tid);
    CP_COMMIT();
    load_stage(sb, 1, Ahi, Alo, Bhi, Blo, aRow0, bRow0, 64, tid);
    CP_COMMIT();

    CLUSTER_SYNC();

    for (int kt = 0; kt < KITERS; ++kt) {
        const int st = kt % STAGES;
        CP_WAIT1();
        __syncthreads();

        if (rank == 1) {
            if (wid == 0 && elect_one_pred()) {
                FENCE_PROXY_ASYNC_SHARED_CTA();
                MBARRIER_ARRIVE_RANK0(sb + SM_FULL(st));
            }
        } else {
            if (wid == 0) {
                mbar_wait_bounded(sb + SM_FULL(st), (uint32_t)((kt / 3) & 1));
                if (elect_one_pred()) {
                    FENCE_PROXY_ASYNC_SHARED_CTA();
                    uint64_t ahi = MAKE_SMEM_DESC(sb + SM_AHI(st));
                    uint64_t alo = MAKE_SMEM_DESC(sb + SM_ALO(st));
                    uint64_t bhi = MAKE_SMEM_DESC(sb + SM_BHI(st));
                    uint64_t blo = MAKE_SMEM_DESC(sb + SM_BLO(st));
                    #pragma unroll
                    for (int s8 = 0; s8 < 4; s8++) {
                        uint64_t o = (uint64_t)(s8 * 2);
                        tcgen05_mma_bf16_cg2(tbase, ahi + o, bhi + o, IDESC_CG2,
                                             (kt == 0 && s8 == 0) ? 0u : 1u);
                        tcgen05_mma_bf16_cg2(tbase, ahi + o, blo + o, IDESC_CG2, 1u);
                        tcgen05_mma_bf16_cg2(tbase, alo + o, bhi + o, IDESC_CG2, 1u);
                    }
                    TCGEN05_COMMIT_MC_CG2(sb + SM_EMPTY(st), 0x3);
                }
            }
        }

        if (kt + 2 < KITERS) {
            int ld = (kt + 2) % STAGES;
            if (kt >= 1)
                mbar_wait_bounded(sb + SM_EMPTY(ld), (uint32_t)(((kt - 1) / 3) & 1));
            load_stage(sb, ld, Ahi, Alo, Bhi, Blo, aRow0, bRow0, (kt + 2) * 64, tid);
        }
        CP_COMMIT();
    }

    if (rank == 0 && wid == 0) {
        if (elect_one_pred()) TCGEN05_COMMIT_MC_CG2(sb + SM_DONE, 0x3);
    }
    mbar_wait_bounded(sb + SM_DONE, 0);
    TCGEN05_FENCE_AFTER();

    // epilogue: warps 0-3, 64 cols (= one head) at a time; optional rope+kappa
    if (wid < 4) {
        int row = m0 + (int)rank * ROWS_CTA + wid * 32 + lid;
        int srow = row & (S - 1);
        float* crow = C + (size_t)row * N + n0;
        for (int cb = 0; cb < PAIR_N; cb += 64) {
            float r[64];
            TCGEN05_LD_32X32B_X32((uint32_t*)r, tbase + cb);
            TCGEN05_LD_32X32B_X32((uint32_t*)(r + 32), tbase + cb + 32);
            TCGEN05_WAIT_LD();
            if (doRope && (n0 + cb) < ROPE_END) {
                #pragma unroll
                for (int j4 = 0; j4 < 32; j4 += 4) {
                    float4 cv = *(const float4*)&g_ropeC[srow * 32 + j4];
                    float4 sv = *(const float4*)&g_ropeS[srow * 32 + j4];
                    #pragma unroll
                    for (int u = 0; u < 4; u++) {
                        int j = j4 + u;
                        float c = (&cv.x)[u], sn = (&sv.x)[u];
                        float x1 = r[j], x2 = r[j + 32];
                        float o1 = x1 * c - x2 * sn;
                        float o2 = x2 * c + x1 * sn;
                        o1 = (o1 > 0.0f) ? (o1 + 1.0f) : expf(o1);
                        o2 = (o2 > 0.0f) ? (o2 + 1.0f) : expf(o2);
                        r[j] = o1;
                        r[j + 32] = o2;
                    }
                }
            }
            #pragma unroll
            for (int j = 0; j < 64; j += 4)
                *(float4*)(crow + cb + j) = make_float4(r[j], r[j + 1], r[j + 2], r[j + 3]);
        }
        TCGEN05_FENCE_BEFORE();
    }
    __syncthreads();
    if (tid == 0) {
        #pragma unroll
        for (int s = 0; s < STAGES; s++) {
            MBARRIER_INVAL(sb + SM_FULL(s));
            MBARRIER_INVAL(sb + SM_EMPTY(s));
        }
        MBARRIER_INVAL(sb + SM_DONE);
    }
    __syncthreads();
    if (wid == 0) {
        TCGEN05_RELINQUISH_CG2();
        TCGEN05_DEALLOC_CG2(tbase, 256);
    }
    CLUSTER_SYNC();
#else
    for (int idx = threadIdx.x; idx < ROWS_CTA * PAIR_N; idx += blockDim.x) {
        int m = m0 + (int)rank * ROWS_CTA + idx / PAIR_N;
        int n = n0 + idx % PAIR_N;
        const __nv_bfloat16* ah = Ahi + (size_t)m * GK;
        const __nv_bfloat16* al = Alo + (size_t)m * GK;
        const __nv_bfloat16* bh = Bhi + (size_t)n * GK;
        const __nv_bfloat16* bl = Blo + (size_t)n * GK;
        float acc = 0.0f;
        for (int k = 0; k < GK; ++k)
            acc = fmaf(__bfloat162float(ah[k]) + __bfloat162float(al[k]),
                       __bfloat162float(bh[k]) + __bfloat162float(bl[k]), acc);
        // fallback rope+kappa (matches epilogue semantics)
        if (doRope && n < ROPE_END) {
            // handled pairwise: only apply when we own j<32 slot AND compute partner
            // simpler: recompute both elements of the pair for the slot we own
            int srow = m & (S - 1);
            int j = n & 63;
            int jj = j & 31;
            float c = g_ropeC[srow * 32 + jj], sn = g_ropeS[srow * 32 + jj];
            // partner value
            int pn = (j < 32) ? (n + 32) : (n - 32);
            const __nv_bfloat16* ph = Bhi + (size_t)pn * GK;
            const __nv_bfloat16* pl = Blo + (size_t)pn * GK;
            float pacc = 0.0f;
            for (int k = 0; k < GK; ++k)
                pacc = fmaf(__bfloat162float(ah[k]) + __bfloat162float(al[k]),
                            __bfloat162float(ph[k]) + __bfloat162float(pl[k]), pacc);
            float o = (j < 32) ? (acc * c - pacc * sn) : (acc * c + pacc * sn);
            acc = (o > 0.0f) ? (o + 1.0f) : expf(o);
        }
        C[(size_t)m * N + n] = acc;
    }
#endif
}

// ---------------- rope table ----------------
__global__ void rope_table_kernel() {
    int i = blockIdx.x * 256 + threadIdx.x;   // [0, S*32)
    int s = i >> 5, j = i & 31;
    float e = (float)(2 * j) / 64.0f;
    float invf = 1.0f / powf(10000.0f, e);
    float ang = (float)s * invf;
    float c, sn;
    sincosf(ang, &sn, &c);
    g_ropeC[i] = c;
    g_ropeS[i] = sn;
}

// ---------------- split: fp32 -> bf16 hi/lo ----------------
__global__ __launch_bounds__(256) void split_kernel(const float* __restrict__ in,
                                                    __nv_bfloat16* __restrict__ hi,
                                                    __nv_bfloat16* __restrict__ lo, long n4) {
    long i = (long)blockIdx.x * blockDim.x + threadIdx.x;
    if (i >= n4) return;
    float4 x = ((const float4*)in)[i];
    __nv_bfloat16 h0, h1, h2, h3, l0, l1, l2, l3;
    bf16_split(x.x, h0, l0);
    bf16_split(x.y, h1, l1);
    bf16_split(x.z, h2, l2);
    bf16_split(x.w, h3, l3);
    __nv_bfloat162* hi2 = (__nv_bfloat162*)hi;
    __nv_bfloat162* lo2 = (__nv_bfloat162*)lo;
    hi2[2 * i]     = __halves2bfloat162(h0, h1);
    hi2[2 * i + 1] = __halves2bfloat162(h2, h3);
    lo2[2 * i]     = __halves2bfloat162(l0, l1);
    lo2[2 * i + 1] = __halves2bfloat162(l2, l3);
}

// ---------------- transpose + split to bf16 hi/lo ----------------
__global__ __launch_bounds__(256) void transpose_split_kernel(const float* __restrict__ in,
                                                              __nv_bfloat16* __restrict__ out_hi,
                                                              __nv_bfloat16* __restrict__ out_lo,
                                                              int R, int Ccols) {
    __shared__ float t[32][33];
    int c0 = blockIdx.x * 32, r0 = blockIdx.y * 32;
    int x = threadIdx.x & 31, y = (threadIdx.x >> 5) * 4;
    #pragma unroll
    for (int i = 0; i < 4; i++)
        t[y + i][x] = in[(size_t)(r0 + y + i) * Ccols + c0 + x];
    __syncthreads();
    #pragma unroll
    for (int i = 0; i < 4; i++) {
        float v = t[x][y + i];
        __nv_bfloat16 h, l;
        bf16_split(v, h, l);
        size_t o = (size_t)(c0 + y + i) * R + r0 + x;
        out_hi[o] = h;
        out_lo[o] = l;
    }
}

// ---------------- zero Qg ----------------
__global__ void zeroQg_kernel() {
    g_Qg[blockIdx.x * 256 + threadIdx.x] = 0.0f;
}

// ---------------- Qg partial: grid (64, 16), atomicAdd of mean contribution ----------
__global__ __launch_bounds__(256) void qg_kernel() {
    int bh = blockIdx.x;
    int sc = blockIdx.y;
    int b = bh / NH, h = bh % NH;
    int d  = threadIdx.x % 64;
    int sg = threadIdx.x / 64;
    int sBeg = sc * (S / 16), sEnd = sBeg + (S / 16);
    float sum = 0.0f;
    for (int s = sBeg + sg; s < sEnd; s += 4)
        sum += g_qkvp[((size_t)b * S + s) * NCAT + QO + h * 64 + d];
    __shared__ float red[256];
    red[threadIdx.x] = sum;
    __syncthreads();
    if (sg == 0) {
        float tot = red[d] + red[64 + d] + red[128 + d] + red[192 + d];
        atomicAdd(&g_Qg[bh * 64 + d], tot / (float)S);
    }
}

// ---------------- logits ----------------
__global__ __launch_bounds__(256) void logits_kernel() {
    int warp = (blockIdx.x * blockDim.x + threadIdx.x) >> 5;
    int lane = threadIdx.x & 31;
    int s = warp % S; int t = warp / S;
    int h = t % NH;   int b = t / NH;
    int hk = h / GROUPS;
    const float* krow = &g_qkvp[((size_t)b * S + s) * NCAT + KO + hk * 64];
    const float* qrow = &g_Qg[(b * NH + h) * 64];
    float sum = krow[lane] * qrow[lane] + krow[lane + 32] * qrow[lane + 32];
    #pragma unroll
    for (int off = 16; off > 0; off >>= 1)
        sum += __shfl_xor_sync(0xffffffffu, sum, off);
    if (lane == 0)
        g_logits[((size_t)b * NH + h) * S + s] = sum;
}

// ---------------- softmax * S ----------------
__global__ __launch_bounds__(256) void softmax_kernel() {
    int bh = blockIdx.x;
    const float* row = &g_logits[(size_t)bh * S];
    __shared__ float red[256];
    float m = -INFINITY;
    for (int i = threadIdx.x; i < S; i += 256) m = fmaxf(m, row[i]);
    red[threadIdx.x] = m; __syncthreads();
    for (int st = 128; st > 0; st >>= 1) {
        if (threadIdx.x < st) red[threadIdx.x] = fmaxf(red[threadIdx.x], red[threadIdx.x + st]);
        __syncthreads();
    }
    m = red[0]; __syncthreads();
    float sum = 0.0f;
    for (int i = threadIdx.x; i < S; i += 256) sum += expf(row[i] - m);
    red[threadIdx.x] = sum; __syncthreads();
    for (int st = 128; st > 0; st >>= 1) {
        if (threadIdx.x < st) red[threadIdx.x] += red[threadIdx.x + st];
        __syncthreads();
    }
    float scale = (float)S / red[0];
    for (int i = threadIdx.x; i < S; i += 256)
        g_alpha[(size_t)bh * S + i] = expf(row[i] - m) * scale;
}

// ---------------- zero g_M ----------------
__global__ __launch_bounds__(256) void zeroM_kernel() {
    int i = blockIdx.x * 256 + threadIdx.x;
    ((float4*)g_M)[i] = make_float4(0.f, 0.f, 0.f, 0.f);
}

// ---------------- outer_sum state (split over S, atomic accumulate) ----------------
#define SCHUNK 8
__global__ __launch_bounds__(256) void outer_kernel() {
    int bh = blockIdx.x;
    int sc = blockIdx.y;
    int b = bh / NH, h = bh % NH, hk = h / GROUPS;
    __shared__ float Ws[32][64];
    __shared__ float Vs[32][64];
    int f = threadIdx.x % 64;
    int g = threadIdx.x / 64;
    float acc[16];
    #pragma unroll
    for (int i = 0; i < 16; i++) acc[i] = 0.0f;

    int sBeg = sc * (S / SCHUNK), sEnd = sBeg + (S / SCHUNK);
    for (int s0 = sBeg; s0 < sEnd; s0 += 32) {
        __syncthreads();
        for (int i = threadIdx.x; i < 32 * 64; i += 256) {
            int s = i / 64, d = i % 64;
            size_t rowb = ((size_t)b * S + s0 + s) * NCAT;
            float a = g_alpha[((size_t)b * NH + h) * S + s0 + s];
            Ws[s][d] = a * g_qkvp[rowb + KO + hk * 64 + d];
            Vs[s][d] = g_qkvp[rowb + VO + hk * 64 + d];
        }
        __syncthreads();
        #pragma unroll 4
        for (int s = 0; s < 32; s++) {
            float vv = Vs[s][f];
            #pragma unroll
            for (int i = 0; i < 16; i++)
                acc[i] = fmaf(Ws[s][g + 4 * i], vv, acc[i]);
        }
    }
    #pragma unroll
    for (int i = 0; i < 16; i++) {
        int d = g + 4 * i;
        atomicAdd(&g_M[((size_t)bh * 64 + d) * 64 + f], acc[i]);
    }
}

// ---------------- ctx = phi * (Qk . M), fused bf16 split into g_Ahi/g_Alo ----------------
__global__ __launch_bounds__(256) void attnmul_kernel() {
    int bh = blockIdx.y;
    int b = bh / NH, h = bh % NH;
    int s0 = blockIdx.x * 64;
    __shared__ float Ms[64][64];
    __shared__ float Qs[64][64];
    for (int i = threadIdx.x; i < 64 * 64; i += 256) {
        Ms[i / 64][i % 64] = g_M[(size_t)bh * 4096 + i];
        int s = i / 64, d = i % 64;
        Qs[s][d] = g_qkvp[((size_t)b * S + s0 + s) * NCAT + QO + h * 64 + d];
    }
    __syncthreads();
    int f = threadIdx.x % 64;
    int sg = threadIdx.x / 64;
    for (int s = sg; s < 64; s += 4) {
        float acc = 0.0f;
        #pragma unroll
        for (int d = 0; d < 64; d++)
            acc = fmaf(Qs[s][d], Ms[d][f], acc);
        size_t row = (size_t)b * S + s0 + s;
        float v = g_qkvp[row * NCAT + PO + h * 64 + f] * acc;
        __nv_bfloat16 hh, ll;
        bf16_split(v, hh, ll);
        size_t o = row * HID + h * 64 + f;
        g_Ahi[o] = hh;
        g_Alo[o] = ll;
    }
}

// ---------------- host launcher ----------------
extern "C" void kernel_launch(void* const* d_in, const int* in_sizes, int n_in,
                              void* d_out, int out_size) {
    const float* hs   = (const float*)d_in[0];
    const float* Wq   = (const float*)d_in[1];
    const float* Wk   = (const float*)d_in[2];
    const float* Wv   = (const float*)d_in[3];
    const float* Wphi = (const float*)d_in[4];
    const float* Wo   = (const float*)d_in[5];
    float* out = (float*)d_out;

    float* qkvp;
    __nv_bfloat16 *Ahi, *Alo, *WcTh, *WcTl, *WoTh, *WoTl;
    cudaGetSymbolAddress((void**)&qkvp, g_qkvp);
    cudaGetSymbolAddress((void**)&Ahi,  g_Ahi);
    cudaGetSymbolAddress((void**)&Alo,  g_Alo);
    cudaGetSymbolAddress((void**)&WcTh, g_WcatT_hi);
    cudaGetSymbolAddress((void**)&WcTl, g_WcatT_lo);
    cudaGetSymbolAddress((void**)&WoTh, g_WoT_hi);
    cudaGetSymbolAddress((void**)&WoTl, g_WoT_lo);

    cudaFuncSetAttribute(tc_gemm, cudaFuncAttributeMaxDynamicSharedMemorySize, SMEM_GEMM);

    // prep: rope table + weight transposes + hs split
    rope_table_kernel<<<(S * 32) / 256, 256>>>();
    transpose_split_kernel<<<dim3(HID / 32, HID / 32), 256>>>(Wq,   WcTh + (size_t)QO * HID, WcTl + (size_t)QO * HID, HID, HID);
    transpose_split_kernel<<<dim3(512 / 32, HID / 32), 256>>>(Wk,   WcTh + (size_t)KO * HID, WcTl + (size_t)KO * HID, HID, 512);
    transpose_split_kernel<<<dim3(512 / 32, HID / 32), 256>>>(Wv,   WcTh + (size_t)VO * HID, WcTl + (size_t)VO * HID, HID, 512);
    transpose_split_kernel<<<dim3(HID / 32, HID / 32), 256>>>(Wphi, WcTh + (size_t)PO * HID, WcTl + (size_t)PO * HID, HID, HID);
    {
        long n4 = (long)BS_ROWS * HID / 4;
        split_kernel<<<(unsigned)((n4 + 255) / 256), 256>>>(hs, Ahi, Alo, n4);
    }

    // fat projection GEMM with fused rope+kappa epilogue
    dim3 gCat(2, NCAT / PAIR_N, BS_ROWS / PAIR_M);   // (2, 20, 32)
    tc_gemm<<<gCat, 256, SMEM_GEMM>>>(Ahi, Alo, WcTh, WcTl, qkvp, NCAT, 1);

    // Wo transpose (independent; overlaps tail of the big GEMM)
    transpose_split_kernel<<<dim3(HID / 32, HID / 32), 256>>>(Wo, WoTh, WoTl, HID, HID);

    zeroQg_kernel<<<B * NH * HD / 256, 256>>>();
    qg_kernel<<<dim3(B * NH, 16), 256>>>();
    logits_kernel<<<(B * NH * S) / 8, 256>>>();
    softmax_kernel<<<B * NH, 256>>>();
    zeroM_kernel<<<(B * NH * HD * HD) / 1024, 256>>>();
    outer_kernel<<<dim3(B * NH, SCHUNK), 256>>>();
    attnmul_kernel<<<dim3(S / 64, B * NH), 256>>>();   // writes bf16 ctx hi/lo directly

    // output projection (no rope)
    dim3 gO(2, HID / PAIR_N, BS_ROWS / PAIR_M);       // (2, 8, 32)
    tc_gemm<<<gO, 256, SMEM_GEMM>>>(Ahi, Alo, WoTh, WoTl, out, HID, 0);
}

// round 13
// speedup vs baseline: 1.1913x; 1.1913x over previous
#include <cuda_runtime.h>
#include <cuda_bf16.h>
#include <math.h>
#include <cstdint>

// ---------------- problem constants ----------------
#define B 2
#define S 4096
#define HID 2048
#define NH 32
#define NKV 8
#define HD 64
#define GROUPS 4
#define BS_ROWS (B * S)     // 8192
#define GK HID              // all GEMMs have K = 2048
#define KITERS (GK / 64)    // 32 k-iterations of 64 bf16 elements

// fat projection output: [8192, 5120] = [q(2048) | k(512) | v(512) | phi(2048)]
#define NCAT 5120
#define QO 0
#define KO 2048
#define VO 2560
#define PO 3072
#define ROPE_END 2560       // cols < ROPE_END get rope+kappa (q and k)

#if defined(__CUDA_ARCH_FEAT_SM103_ALL) || defined(__CUDA_ARCH_FEAT_SM100_ALL)
#define HAS_TCGEN05 1
#else
#define HAS_TCGEN05 0
#endif

// ---------------- generic ptx helpers ----------------
__device__ __forceinline__ uint32_t elect_one_pred() {
    uint32_t pred;
    asm volatile(
        "{\n\t.reg .pred p;\n\t"
        "elect.sync _|p, 0xFFFFFFFF;\n\t"
        "selp.b32 %0, 1, 0, p;\n\t}"
        : "=r"(pred));
    return pred;
}

__device__ __forceinline__ uint32_t smem_u32(const void* p) {
    uint32_t a;
    asm("{ .reg .u64 t; cvta.to.shared.u64 t, %1; cvt.u32.u64 %0, t; }" : "=r"(a) : "l"(p));
    return a;
}

__device__ __forceinline__ uint32_t cluster_rank() {
    uint32_t r;
    asm("mov.u32 %0, %%cluster_ctarank;" : "=r"(r));
    return r;
}

// bf16 2-way split: x = hi + lo, hi = bf16_rn(x)
__device__ __forceinline__ void bf16_split(float x, __nv_bfloat16& h, __nv_bfloat16& l) {
    h = __float2bfloat16(x);
    l = __float2bfloat16(x - __bfloat162float(h));
}

#define MBARRIER_INIT(addr, cnt) \
    asm volatile("mbarrier.init.shared.b64 [%0], %1;" :: "r"((uint32_t)(addr)), "r"((uint32_t)(cnt)) : "memory")
#define MBARRIER_INVAL(addr) \
    asm volatile("mbarrier.inval.shared.b64 [%0];" :: "r"((uint32_t)(addr)) : "memory")

#define MBARRIER_ARRIVE_RANK0(local_addr) \
    asm volatile( \
        "{\n\t.reg .b32 remAddr;\n\t" \
        "mapa.shared::cluster.u32 remAddr, %0, 0;\n\t" \
        "mbarrier.arrive.shared::cluster.b64 _, [remAddr];\n\t}" \
        :: "r"((uint32_t)(local_addr)) : "memory")

// BOUNDED wait (~250K polls): broken protocol finishes fast + observable.
__device__ __forceinline__ void mbar_wait_bounded(uint32_t mbar, uint32_t parity) {
    uint32_t done = 0;
    for (int i = 0; i < 250000; ++i) {
        asm volatile(
            "{\n\t.reg .pred p;\n\t"
            "mbarrier.try_wait.parity.acquire.cta.shared::cta.b64 p, [%1], %2;\n\t"
            "selp.b32 %0, 1, 0, p;\n\t}"
            : "=r"(done) : "r"(mbar), "r"(parity) : "memory");
        if (done) break;
    }
}

#define SWZ(o) ((o) ^ (((o) >> 3) & 0x70))

__device__ __forceinline__ void cp_async16(uint32_t dst, const void* src) {
    asm volatile("cp.async.cg.shared.global [%0], [%1], 16;" :: "r"(dst), "l"(src));
}
#define CP_COMMIT() asm volatile("cp.async.commit_group;" ::: "memory")
#define CP_WAIT1()  asm volatile("cp.async.wait_group 1;" ::: "memory")
#define FENCE_PROXY_ASYNC_SHARED_CTA() asm volatile("fence.proxy.async.shared::cta;" ::: "memory")
#define CLUSTER_SYNC() do { \
    asm volatile("barrier.cluster.arrive.aligned;" ::: "memory"); \
    asm volatile("barrier.cluster.wait.aligned;" ::: "memory"); \
} while (0)

// ---------------- tcgen05 helpers (guarded, cta_group::2) ----------------
#if HAS_TCGEN05
#define TCGEN05_ALLOC_CG2(smem_result_addr, nCols) \
    asm volatile("tcgen05.alloc.cta_group::2.sync.aligned.shared::cta.b32 [%0], %1;" \
        :: "r"((uint32_t)(smem_result_addr)), "r"((uint32_t)(nCols)) : "memory")
#define TCGEN05_DEALLOC_CG2(tmem_addr, nCols) \
    asm volatile("tcgen05.dealloc.cta_group::2.sync.aligned.b32 %0, %1;" :: "r"(tmem_addr), "r"((uint32_t)(nCols)))
#define TCGEN05_RELINQUISH_CG2() \
    asm volatile("tcgen05.relinquish_alloc_permit.cta_group::2.sync.aligned;")
#define TCGEN05_COMMIT_MC_CG2(mbar_smem_addr, mask) \
    asm volatile("tcgen05.commit.cta_group::2.mbarrier::arrive::one.shared::cluster.multicast::cluster.b64 [%0], %1;" \
        :: "r"((uint32_t)(mbar_smem_addr)), "h"((uint16_t)(mask)) : "memory")
#define TCGEN05_WAIT_LD()  asm volatile("tcgen05.wait::ld.sync.aligned;" ::: "memory")
#define TCGEN05_FENCE_AFTER()  asm volatile("tcgen05.fence::after_thread_sync;" ::: "memory")
#define TCGEN05_FENCE_BEFORE() asm volatile("tcgen05.fence::before_thread_sync;" ::: "memory")

#define TCGEN05_LD_32X32B_X32(r, tmem_addr) \
    asm volatile( \
        "tcgen05.ld.sync.aligned.32x32b.x32.b32 " \
        "{%0, %1, %2, %3, %4, %5, %6, %7, " \
        " %8, %9, %10, %11, %12, %13, %14, %15, " \
        " %16, %17, %18, %19, %20, %21, %22, %23, " \
        " %24, %25, %26, %27, %28, %29, %30, %31}, [%32];" \
        : "=r"((r)[0]),  "=r"((r)[1]),  "=r"((r)[2]),  "=r"((r)[3]), \
          "=r"((r)[4]),  "=r"((r)[5]),  "=r"((r)[6]),  "=r"((r)[7]), \
          "=r"((r)[8]),  "=r"((r)[9]),  "=r"((r)[10]), "=r"((r)[11]), \
          "=r"((r)[12]), "=r"((r)[13]), "=r"((r)[14]), "=r"((r)[15]), \
          "=r"((r)[16]), "=r"((r)[17]), "=r"((r)[18]), "=r"((r)[19]), \
          "=r"((r)[20]), "=r"((r)[21]), "=r"((r)[22]), "=r"((r)[23]), \
          "=r"((r)[24]), "=r"((r)[25]), "=r"((r)[26]), "=r"((r)[27]), \
          "=r"((r)[28]), "=r"((r)[29]), "=r"((r)[30]), "=r"((r)[31]) \
        : "r"(tmem_addr))

// bf16 cg2 SS MMA (kind::f16) with disable-output-lane vector (8 regs, all 0)
__device__ __forceinline__ void tcgen05_mma_bf16_cg2(uint32_t d, uint64_t ad, uint64_t bd,
                                                     uint32_t idesc, uint32_t en) {
    asm volatile(
        "{\n\t.reg .pred p;\n\t"
        "setp.ne.u32 p, %5, 0;\n\t"
        "tcgen05.mma.cta_group::2.kind::f16 [%0], %1, %2, %3, "
        "{%4, %4, %4, %4, %4, %4, %4, %4}, p;\n\t}"
        :: "r"(d), "l"(ad), "l"(bd), "r"(idesc), "r"(0u), "r"(en) : "memory");
}
#endif // HAS_TCGEN05

static constexpr uint64_t SMEM_DESC_BASE_SW128 =
    (uint64_t(2) << 61) | (uint64_t(1) << 46) | (uint64_t(64) << 32) | (uint64_t(1) << 16);
#define MAKE_SMEM_DESC(base_addr) (SMEM_DESC_BASE_SW128 | ((uint64_t)((base_addr) >> 4) & 0x3FFF))

// ---------------- scratch (static device globals; 256B-aligned) ----------------
__device__ __align__(256) float g_qkvp[(size_t)BS_ROWS * NCAT];   // fat projection output
__device__ __align__(256) float g_ropeC[S * 32];                  // cos table
__device__ __align__(256) float g_ropeS[S * 32];                  // sin table
__device__ __align__(256) float g_Qg [B * NH * HD];
__device__ __align__(256) float g_alpha [B * NH * S];
__device__ __align__(256) float g_M  [B * NH * HD * HD];
__device__ __align__(256) __nv_bfloat16 g_Ahi[(size_t)BS_ROWS * HID];
__device__ __align__(256) __nv_bfloat16 g_Alo[(size_t)BS_ROWS * HID];
__device__ __align__(256) __nv_bfloat16 g_WcatT_hi[(size_t)NCAT * HID];
__device__ __align__(256) __nv_bfloat16 g_WcatT_lo[(size_t)NCAT * HID];
__device__ __align__(256) __nv_bfloat16 g_WoT_hi  [HID * HID];
__device__ __align__(256) __nv_bfloat16 g_WoT_lo  [HID * HID];

// ---------------- cg2 3-term bf16 GEMM -----------------------------------------
#define ROWS_CTA 128
#define PAIR_M 256
#define PAIR_N 256
#define STAGES 3
#define REGION_BYTES (ROWS_CTA * 128)         // 16KB
#define STAGE_BYTES (4 * REGION_BYTES)        // 64KB
#define SM_FULL(s)  (8  + (s) * 8)
#define SM_EMPTY(s) (32 + (s) * 8)
#define SM_DONE 56
#define SM_AHI(s) (1024 + (s) * STAGE_BYTES)
#define SM_ALO(s) (SM_AHI(s) + REGION_BYTES)
#define SM_BHI(s) (SM_AHI(s) + 2 * REGION_BYTES)
#define SM_BLO(s) (SM_AHI(s) + 3 * REGION_BYTES)
#define SMEM_GEMM (1024 + STAGES * STAGE_BYTES)   // 197632 bytes

static constexpr uint32_t IDESC_CG2 =
    (1u << 4)              // dtype F32
  | (1u << 7)              // atype BF16
  | (1u << 10)             // btype BF16
  | ((PAIR_N / 8) << 17)   // N = 256
  | ((PAIR_M / 16) << 24); // M = 256

__device__ __forceinline__ void load_region(uint32_t dst, const __nv_bfloat16* __restrict__ src,
                                            int row0, int k0, int tid) {
    #pragma unroll
    for (int i = 0; i < 4; i++) {
        int chunk = i * 256 + tid;
        int row = chunk >> 3, c = chunk & 7;
        uint32_t off = (uint32_t)(row * 128 + c * 16);
        cp_async16(dst + SWZ(off), src + (size_t)(row0 + row) * GK + k0 + c * 8);
    }
}

__device__ __forceinline__ void load_stage(uint32_t sb, int st,
                                           const __nv_bfloat16* __restrict__ Ahi,
                                           const __nv_bfloat16* __restrict__ Alo,
                                           const __nv_bfloat16* __restrict__ Bhi,
                                           const __nv_bfloat16* __restrict__ Blo,
                                           int aRow0, int bRow0, int k0, int tid) {
    load_region(sb + SM_AHI(st), Ahi, aRow0, k0, tid);
    load_region(sb + SM_ALO(st), Alo, aRow0, k0, tid);
    load_region(sb + SM_BHI(st), Bhi, bRow0, k0, tid);
    load_region(sb + SM_BLO(st), Blo, bRow0, k0, tid);
}

// doRope != 0: columns < ROPE_END of the output get RoPE + kappa in the epilogue.
__global__ __launch_bounds__(256, 1) __cluster_dims__(2, 1, 1)
void tc_gemm(const __nv_bfloat16* __restrict__ Ahi, const __nv_bfloat16* __restrict__ Alo,
             const __nv_bfloat16* __restrict__ Bhi, const __nv_bfloat16* __restrict__ Blo,
             float* __restrict__ C, int N, int doRope) {
    const uint32_t rank = cluster_rank();
    const int m0 = blockIdx.z * PAIR_M;
    const int n0 = blockIdx.y * PAIR_N;
#if HAS_TCGEN05
    extern __shared__ char smem[];
    uint32_t sb = smem_u32(smem);
    const int tid = threadIdx.x;
    const int wid = tid >> 5, lid = tid & 31;
    const int aRow0 = m0 + (int)rank * ROWS_CTA;
    const int bRow0 = n0 + (int)rank * ROWS_CTA;

    if (tid == 0) {
        #pragma unroll
        for (int s = 0; s < STAGES; s++) {
            MBARRIER_INIT(sb + SM_FULL(s), 1);
            MBARRIER_INIT(sb + SM_EMPTY(s), 1);
        }
        MBARRIER_INIT(sb + SM_DONE, 1);
    }
    __syncthreads();
    if (wid == 0) TCGEN05_ALLOC_CG2(sb, 256);
    __syncthreads();
    uint32_t tbase;
    asm volatile("ld.shared.b32 %0, [%1];" : "=r"(tbase) : "r"(sb));

    load_stage(sb, 0, Ahi, Alo, Bhi, Blo, aRow0, bRow0, 0, tid);
    CP_COMMIT();
    load_stage(sb, 1, Ahi, Alo, Bhi, Blo, aRow0, bRow0, 64, tid);
    CP_COMMIT();

    CLUSTER_SYNC();

    for (int kt = 0; kt < KITERS; ++kt) {
        const int st = kt % STAGES;
        CP_WAIT1();
        __syncthreads();

        if (rank == 1) {
            if (wid == 0 && elect_one_pred()) {
                FENCE_PROXY_ASYNC_SHARED_CTA();
                MBARRIER_ARRIVE_RANK0(sb + SM_FULL(st));
            }
        } else {
            if (wid == 0) {
                mbar_wait_bounded(sb + SM_FULL(st), (uint32_t)((kt / 3) & 1));
                if (elect_one_pred()) {
                    FENCE_PROXY_ASYNC_SHARED_CTA();
                    uint64_t ahi = MAKE_SMEM_DESC(sb + SM_AHI(st));
                    uint64_t alo = MAKE_SMEM_DESC(sb + SM_ALO(st));
                    uint64_t bhi = MAKE_SMEM_DESC(sb + SM_BHI(st));
                    uint64_t blo = MAKE_SMEM_DESC(sb + SM_BLO(st));
                    #pragma unroll
                    for (int s8 = 0; s8 < 4; s8++) {
                        uint64_t o = (uint64_t)(s8 * 2);
                        tcgen05_mma_bf16_cg2(tbase, ahi + o, bhi + o, IDESC_CG2,
                                             (kt == 0 && s8 == 0) ? 0u : 1u);
                        tcgen05_mma_bf16_cg2(tbase, ahi + o, blo + o, IDESC_CG2, 1u);
                        tcgen05_mma_bf16_cg2(tbase, alo + o, bhi + o, IDESC_CG2, 1u);
                    }
                    TCGEN05_COMMIT_MC_CG2(sb + SM_EMPTY(st), 0x3);
                }
            }
        }

        if (kt + 2 < KITERS) {
            int ld = (kt + 2) % STAGES;
            if (kt >= 1)
                mbar_wait_bounded(sb + SM_EMPTY(ld), (uint32_t)(((kt - 1) / 3) & 1));
            load_stage(sb, ld, Ahi, Alo, Bhi, Blo, aRow0, bRow0, (kt + 2) * 64, tid);
        }
        CP_COMMIT();
    }

    if (rank == 0 && wid == 0) {
        if (elect_one_pred()) TCGEN05_COMMIT_MC_CG2(sb + SM_DONE, 0x3);
    }
    mbar_wait_bounded(sb + SM_DONE, 0);
    TCGEN05_FENCE_AFTER();

    // epilogue: warps 0-3, 64 cols (= one head) at a time; optional rope+kappa
    if (wid < 4) {
        int row = m0 + (int)rank * ROWS_CTA + wid * 32 + lid;
        int srow = row & (S - 1);
        float* crow = C + (size_t)row * N + n0;
        for (int cb = 0; cb < PAIR_N; cb += 64) {
            float r[64];
            TCGEN05_LD_32X32B_X32((uint32_t*)r, tbase + cb);
            TCGEN05_LD_32X32B_X32((uint32_t*)(r + 32), tbase + cb + 32);
            TCGEN05_WAIT_LD();
            if (doRope && (n0 + cb) < ROPE_END) {
                #pragma unroll
                for (int j4 = 0; j4 < 32; j4 += 4) {
                    float4 cv = *(const float4*)&g_ropeC[srow * 32 + j4];
                    float4 sv = *(const float4*)&g_ropeS[srow * 32 + j4];
                    #pragma unroll
                    for (int u = 0; u < 4; u++) {
                        int j = j4 + u;
                        float c = (&cv.x)[u], sn = (&sv.x)[u];
                        float x1 = r[j], x2 = r[j + 32];
                        float o1 = x1 * c - x2 * sn;
                        float o2 = x2 * c + x1 * sn;
                        o1 = (o1 > 0.0f) ? (o1 + 1.0f) : expf(o1);
                        o2 = (o2 > 0.0f) ? (o2 + 1.0f) : expf(o2);
                        r[j] = o1;
                        r[j + 32] = o2;
                    }
                }
            }
            #pragma unroll
            for (int j = 0; j < 64; j += 4)
                *(float4*)(crow + cb + j) = make_float4(r[j], r[j + 1], r[j + 2], r[j + 3]);
        }
        TCGEN05_FENCE_BEFORE();
    }
    __syncthreads();
    if (tid == 0) {
        #pragma unroll
        for (int s = 0; s < STAGES; s++) {
            MBARRIER_INVAL(sb + SM_FULL(s));
            MBARRIER_INVAL(sb + SM_EMPTY(s));
        }
        MBARRIER_INVAL(sb + SM_DONE);
    }
    __syncthreads();
    if (wid == 0) {
        TCGEN05_RELINQUISH_CG2();
        TCGEN05_DEALLOC_CG2(tbase, 256);
    }
    CLUSTER_SYNC();
#else
    for (int idx = threadIdx.x; idx < ROWS_CTA * PAIR_N; idx += blockDim.x) {
        int m = m0 + (int)rank * ROWS_CTA + idx / PAIR_N;
        int n = n0 + idx % PAIR_N;
        const __nv_bfloat16* ah = Ahi + (size_t)m * GK;
        const __nv_bfloat16* al = Alo + (size_t)m * GK;
        const __nv_bfloat16* bh = Bhi + (size_t)n * GK;
        const __nv_bfloat16* bl = Blo + (size_t)n * GK;
        float acc = 0.0f;
        for (int k = 0; k < GK; ++k)
            acc = fmaf(__bfloat162float(ah[k]) + __bfloat162float(al[k]),
                       __bfloat162float(bh[k]) + __bfloat162float(bl[k]), acc);
        if (doRope && n < ROPE_END) {
            int srow = m & (S - 1);
            int j = n & 63;
            int jj = j & 31;
            float c = g_ropeC[srow * 32 + jj], sn = g_ropeS[srow * 32 + jj];
            int pn = (j < 32) ? (n + 32) : (n - 32);
            const __nv_bfloat16* ph = Bhi + (size_t)pn * GK;
            const __nv_bfloat16* pl = Blo + (size_t)pn * GK;
            float pacc = 0.0f;
            for (int k = 0; k < GK; ++k)
                pacc = fmaf(__bfloat162float(ah[k]) + __bfloat162float(al[k]),
                            __bfloat162float(ph[k]) + __bfloat162float(pl[k]), pacc);
            float o = (j < 32) ? (acc * c - pacc * sn) : (acc * c + pacc * sn);
            acc = (o > 0.0f) ? (o + 1.0f) : expf(o);
        }
        C[(size_t)m * N + n] = acc;
    }
#endif
}

// ---------------- prep: rope table + zero Qg + zero M (one launch) ----------------
__global__ void prep_misc_kernel() {
    int i = blockIdx.x * 256 + threadIdx.x;       // grid 512 -> 131072 threads
    if (i < S * 32) {
        int s = i >> 5, j = i & 31;
        float e = (float)(2 * j) / 64.0f;
        float invf = 1.0f / powf(10000.0f, e);
        float ang = (float)s * invf;
        float c, sn;
        sincosf(ang, &sn, &c);
        g_ropeC[i] = c;
        g_ropeS[i] = sn;
    }
    if (i < B * NH * HD) g_Qg[i] = 0.0f;
    if (i < (B * NH * HD * HD) / 4)
        ((float4*)g_M)[i] = make_float4(0.f, 0.f, 0.f, 0.f);
}

// ---------------- split: fp32 -> bf16 hi/lo ----------------
__global__ __launch_bounds__(256) void split_kernel(const float* __restrict__ in,
                                                    __nv_bfloat16* __restrict__ hi,
                                                    __nv_bfloat16* __restrict__ lo, long n4) {
    long i = (long)blockIdx.x * blockDim.x + threadIdx.x;
    if (i >= n4) return;
    float4 x = ((const float4*)in)[i];
    __nv_bfloat16 h0, h1, h2, h3, l0, l1, l2, l3;
    bf16_split(x.x, h0, l0);
    bf16_split(x.y, h1, l1);
    bf16_split(x.z, h2, l2);
    bf16_split(x.w, h3, l3);
    __nv_bfloat162* hi2 = (__nv_bfloat162*)hi;
    __nv_bfloat162* lo2 = (__nv_bfloat162*)lo;
    hi2[2 * i]     = __halves2bfloat162(h0, h1);
    hi2[2 * i + 1] = __halves2bfloat162(h2, h3);
    lo2[2 * i]     = __halves2bfloat162(l0, l1);
    lo2[2 * i + 1] = __halves2bfloat162(l2, l3);
}

// ---------------- merged transpose+split of ALL 5 weights (one launch) ----------------
__global__ __launch_bounds__(256) void transpose_all_kernel(const float* __restrict__ W0,
                                                            const float* __restrict__ W1,
                                                            const float* __restrict__ W2,
                                                            const float* __restrict__ W3,
                                                            const float* __restrict__ W4) {
    const float* in;
    int Ccols;
    __nv_bfloat16 *oh, *ol;
    switch (blockIdx.z) {
        case 0:  in = W0; Ccols = HID; oh = g_WcatT_hi + (size_t)QO * HID; ol = g_WcatT_lo + (size_t)QO * HID; break;
        case 1:  in = W1; Ccols = 512; oh = g_WcatT_hi + (size_t)KO * HID; ol = g_WcatT_lo + (size_t)KO * HID; break;
        case 2:  in = W2; Ccols = 512; oh = g_WcatT_hi + (size_t)VO * HID; ol = g_WcatT_lo + (size_t)VO * HID; break;
        case 3:  in = W3; Ccols = HID; oh = g_WcatT_hi + (size_t)PO * HID; ol = g_WcatT_lo + (size_t)PO * HID; break;
        default: in = W4; Ccols = HID; oh = g_WoT_hi;                     ol = g_WoT_lo;                     break;
    }
    int c0 = blockIdx.x * 32, r0 = blockIdx.y * 32;
    if (c0 >= Ccols) return;
    __shared__ float t[32][33];
    int x = threadIdx.x & 31, y = (threadIdx.x >> 5) * 4;
    #pragma unroll
    for (int i = 0; i < 4; i++)
        t[y + i][x] = in[(size_t)(r0 + y + i) * Ccols + c0 + x];
    __syncthreads();
    #pragma unroll
    for (int i = 0; i < 4; i++) {
        float v = t[x][y + i];
        __nv_bfloat16 h, l;
        bf16_split(v, h, l);
        size_t o = (size_t)(c0 + y + i) * GK + r0 + x;
        oh[o] = h;
        ol[o] = l;
    }
}

// ---------------- Qg partial: grid (64, 16), atomicAdd of mean contribution ----------
__global__ __launch_bounds__(256) void qg_kernel() {
    int bh = blockIdx.x;
    int sc = blockIdx.y;
    int b = bh / NH, h = bh % NH;
    int d  = threadIdx.x % 64;
    int sg = threadIdx.x / 64;
    int sBeg = sc * (S / 16), sEnd = sBeg + (S / 16);
    float sum = 0.0f;
    for (int s = sBeg + sg; s < sEnd; s += 4)
        sum += g_qkvp[((size_t)b * S + s) * NCAT + QO + h * 64 + d];
    __shared__ float red[256];
    red[threadIdx.x] = sum;
    __syncthreads();
    if (sg == 0) {
        float tot = red[d] + red[64 + d] + red[128 + d] + red[192 + d];
        atomicAdd(&g_Qg[bh * 64 + d], tot / (float)S);
    }
}

// ---------------- merged logits + softmax: one block per (b,h) ----------------
__global__ __launch_bounds__(256) void alpha_kernel() {
    int bh = blockIdx.x;
    int b = bh / NH, h = bh % NH, hk = h / GROUPS;
    __shared__ float qg[64];
    __shared__ float lg[S];          // 16 KB
    __shared__ float red[256];
    if (threadIdx.x < 64) qg[threadIdx.x] = g_Qg[bh * 64 + threadIdx.x];
    __syncthreads();

    float lmax = -INFINITY;
    for (int s = threadIdx.x; s < S; s += 256) {
        const float* krow = &g_qkvp[((size_t)b * S + s) * NCAT + KO + hk * 64];
        float acc = 0.0f;
        #pragma unroll
        for (int d = 0; d < 64; d += 4) {
            float4 kv = *(const float4*)&krow[d];
            acc = fmaf(kv.x, qg[d], acc);
            acc = fmaf(kv.y, qg[d + 1], acc);
            acc = fmaf(kv.z, qg[d + 2], acc);
            acc = fmaf(kv.w, qg[d + 3], acc);
        }
        lg[s] = acc;
        lmax = fmaxf(lmax, acc);
    }
    red[threadIdx.x] = lmax; __syncthreads();
    for (int st = 128; st > 0; st >>= 1) {
        if (threadIdx.x < st) red[threadIdx.x] = fmaxf(red[threadIdx.x], red[threadIdx.x + st]);
        __syncthreads();
    }
    float m = red[0]; __syncthreads();

    float lsum = 0.0f;
    for (int s = threadIdx.x; s < S; s += 256) {
        float e = expf(lg[s] - m);
        lg[s] = e;
        lsum += e;
    }
    red[threadIdx.x] = lsum; __syncthreads();
    for (int st = 128; st > 0; st >>= 1) {
        if (threadIdx.x < st) red[threadIdx.x] += red[threadIdx.x + st];
        __syncthreads();
    }
    float scale = (float)S / red[0];
    for (int s = threadIdx.x; s < S; s += 256)
        g_alpha[(size_t)bh * S + s] = lg[s] * scale;
}

// ---------------- outer_sum (register-tiled 8d x 2f per thread) ----------------
#define SCHUNK 8
__global__ __launch_bounds__(256) void outer_kernel() {
    int bh = blockIdx.x;
    int sc = blockIdx.y;
    int b = bh / NH, h = bh % NH, hk = h / GROUPS;
    __shared__ float Ws[32][64];
    __shared__ float Vs[32][64];
    int f2 = threadIdx.x & 31;        // f in {f2, f2+32}
    int g8 = threadIdx.x >> 5;        // d in {g8 + 8i}
    float acc[8][2];
    #pragma unroll
    for (int i = 0; i < 8; i++) { acc[i][0] = 0.0f; acc[i][1] = 0.0f; }

    int sBeg = sc * (S / SCHUNK), sEnd = sBeg + (S / SCHUNK);
    for (int s0 = sBeg; s0 < sEnd; s0 += 32) {
        __syncthreads();
        for (int i = threadIdx.x; i < 32 * 64; i += 256) {
            int s = i / 64, d = i % 64;
            size_t rowb = ((size_t)b * S + s0 + s) * NCAT;
            float a = g_alpha[((size_t)b * NH + h) * S + s0 + s];
            Ws[s][d] = a * g_qkvp[rowb + KO + hk * 64 + d];
            Vs[s][d] = g_qkvp[rowb + VO + hk * 64 + d];
        }
        __syncthreads();
        #pragma unroll 4
        for (int s = 0; s < 32; s++) {
            float v0 = Vs[s][f2];
            float v1 = Vs[s][f2 + 32];
            #pragma unroll
            for (int i = 0; i < 8; i++) {
                float w = Ws[s][g8 + 8 * i];
                acc[i][0] = fmaf(w, v0, acc[i][0]);
                acc[i][1] = fmaf(w, v1, acc[i][1]);
            }
        }
    }
    #pragma unroll
    for (int i = 0; i < 8; i++) {
        int d = g8 + 8 * i;
        atomicAdd(&g_M[((size_t)bh * 64 + d) * 64 + f2],      acc[i][0]);
        atomicAdd(&g_M[((size_t)bh * 64 + d) * 64 + f2 + 32], acc[i][1]);
    }
}

// ---------------- ctx = phi * (Qk . M), register-tiled 8s x 2f, bf16 split ------
__global__ __launch_bounds__(256) void attnmul_kernel() {
    int bh = blockIdx.y;
    int b = bh / NH, h = bh % NH;
    int s0 = blockIdx.x * 64;
    __shared__ float Ms[64][64];
    __shared__ float Qs[64][64];
    for (int i = threadIdx.x; i < 64 * 64; i += 256) {
        Ms[i / 64][i % 64] = g_M[(size_t)bh * 4096 + i];
        int s = i / 64, d = i % 64;
        Qs[s][d] = g_qkvp[((size_t)b * S + s0 + s) * NCAT + QO + h * 64 + d];
    }
    __syncthreads();
    int f2 = threadIdx.x & 31;        // f in {f2, f2+32}
    int sg = threadIdx.x >> 5;        // s in {sg + 8i}
    float acc[8][2];
    #pragma unroll
    for (int i = 0; i < 8; i++) { acc[i][0] = 0.0f; acc[i][1] = 0.0f; }

    #pragma unroll 8
    for (int d = 0; d < 64; d++) {
        float m0 = Ms[d][f2];
        float m1 = Ms[d][f2 + 32];
        #pragma unroll
        for (int i = 0; i < 8; i++) {
            float q = Qs[sg + 8 * i][d];
            acc[i][0] = fmaf(q, m0, acc[i][0]);
            acc[i][1] = fmaf(q, m1, acc[i][1]);
        }
    }
    #pragma unroll
    for (int i = 0; i < 8; i++) {
        int s = sg + 8 * i;
        size_t row = (size_t)b * S + s0 + s;
        float p0 = g_qkvp[row * NCAT + PO + h * 64 + f2];
        float p1 = g_qkvp[row * NCAT + PO + h * 64 + f2 + 32];
        float v0 = p0 * acc[i][0];
        float v1 = p1 * acc[i][1];
        __nv_bfloat16 hh, ll;
        bf16_split(v0, hh, ll);
        g_Ahi[row * HID + h * 64 + f2] = hh;
        g_Alo[row * HID + h * 64 + f2] = ll;
        bf16_split(v1, hh, ll);
        g_Ahi[row * HID + h * 64 + f2 + 32] = hh;
        g_Alo[row * HID + h * 64 + f2 + 32] = ll;
    }
}

// ---------------- host launcher ----------------
extern "C" void kernel_launch(void* const* d_in, const int* in_sizes, int n_in,
                              void* d_out, int out_size) {
    const float* hs   = (const float*)d_in[0];
    const float* Wq   = (const float*)d_in[1];
    const float* Wk   = (const float*)d_in[2];
    const float* Wv   = (const float*)d_in[3];
    const float* Wphi = (const float*)d_in[4];
    const float* Wo   = (const float*)d_in[5];
    float* out = (float*)d_out;

    float* qkvp;
    __nv_bfloat16 *Ahi, *Alo, *WcTh, *WcTl, *WoTh, *WoTl;
    cudaGetSymbolAddress((void**)&qkvp, g_qkvp);
    cudaGetSymbolAddress((void**)&Ahi,  g_Ahi);
    cudaGetSymbolAddress((void**)&Alo,  g_Alo);
    cudaGetSymbolAddress((void**)&WcTh, g_WcatT_hi);
    cudaGetSymbolAddress((void**)&WcTl, g_WcatT_lo);
    cudaGetSymbolAddress((void**)&WoTh, g_WoT_hi);
    cudaGetSymbolAddress((void**)&WoTl, g_WoT_lo);

    cudaFuncSetAttribute(tc_gemm, cudaFuncAttributeMaxDynamicSharedMemorySize, SMEM_GEMM);

    // prep (rope table + zeros), merged transposes, hs split
    prep_misc_kernel<<<512, 256>>>();
    transpose_all_kernel<<<dim3(HID / 32, HID / 32, 5), 256>>>(Wq, Wk, Wv, Wphi, Wo);
    {
        long n4 = (long)BS_ROWS * HID / 4;
        split_kernel<<<(unsigned)((n4 + 255) / 256), 256>>>(hs, Ahi, Alo, n4);
    }

    // fat projection GEMM with fused rope+kappa epilogue
    dim3 gCat(2, NCAT / PAIR_N, BS_ROWS / PAIR_M);   // (2, 20, 32)
    tc_gemm<<<gCat, 256, SMEM_GEMM>>>(Ahi, Alo, WcTh, WcTl, qkvp, NCAT, 1);

    // attention chain
    qg_kernel<<<dim3(B * NH, 16), 256>>>();
    alpha_kernel<<<B * NH, 256>>>();
    outer_kernel<<<dim3(B * NH, SCHUNK), 256>>>();
    attnmul_kernel<<<dim3(S / 64, B * NH), 256>>>();

    // output projection (no rope)
    dim3 gO(2, HID / PAIR_N, BS_ROWS / PAIR_M);       // (2, 8, 32)
    tc_gemm<<<gO, 256, SMEM_GEMM>>>(Ahi, Alo, WoTh, WoTl, out, HID, 0);
}